// round 16
// baseline (speedup 1.0000x reference)
#include <cuda_runtime.h>
#include <cuda_fp16.h>

#define NN 50000
#define NE 800000
#define D 64
#define LL 4
#define GG 128
#define TT 10
#define NEG_SLOPE 0.2f
#define EPSV 1e-16f
#define NBLK ((NN + 255) / 256)   // 196
#define NV 21                     // node vocab size
#define NORMB 12500               // agg blocks: warp per node, 4/block
#define BIGB 8                    // trailing agg blocks for deg>32 nodes
#define MAXBIG 8192

// ---------------- scratch (static __device__, zero-init at load) ----------------
__device__ int   g_deg[NN];        // zeroed by scatter_kernel at end of each run
__device__ int   g_rowptr[NN + 1];
__device__ int   g_erank[NE];      // per-edge rank within dst node (from hist)
__device__ unsigned g_epoch;                    // monotonic run counter
__device__ volatile unsigned g_aggflag[NBLK];   // epoch-tagged publish flags
__device__ volatile int      g_aggval[NBLK];
__device__ int   g_bigcnt;
__device__ int   g_biglist[MAXBIG];
__device__ int   g_csr[NE];        // packed (attr<<24) | src
__device__ float g_alpha[NE];      // big-node fallback scratch
__device__ __align__(16) __half g_h16A[NN * D];     // h buffers in fp16
__device__ __align__(16) __half g_h16B[NN * D];
__device__ __align__(16) __half g_gbuf16[NN * D];   // g in fp16 (1 line / row)
__device__ float g_asrc[NN];
__device__ float2 g_nodeinfo[NN];  // .x = int bits: (start<<8)|min(deg,255); .y = adst
__device__ float g_ewalpha[LL * 4];
__device__ __align__(16) __half g_gt16[NV * D];     // layer-0 g table (fp16)
__device__ float g_ast[NV];        // layer-0 asrc table
__device__ float g_adt[NV];        // layer-0 adst table

// ---------------- hist: 4 edges/thread, capture per-edge rank ----------------
__global__ void hist_kernel(const int* __restrict__ dst) {
    int t = blockIdx.x * 256 + threadIdx.x;
    int e = t * 4;
    if (e < NE) {   // NE % 4 == 0
        int4 d = *(const int4*)(dst + e);
        int4 r;
        r.x = atomicAdd(&g_deg[d.x], 1);
        r.y = atomicAdd(&g_deg[d.y], 1);
        r.z = atomicAdd(&g_deg[d.z], 1);
        r.w = atomicAdd(&g_deg[d.w], 1);
        *(int4*)(g_erank + e) = r;
    }
}

// ---------------- pre: epoch + ewalpha + layer-0 tables (single block) ----------------
__global__ void pre_kernel(const float* __restrict__ edge_embs,
                           const float* __restrict__ W_edges,
                           const float* __restrict__ att_edge,
                           const float* __restrict__ node_emb,
                           const float* __restrict__ Ws,
                           const float* __restrict__ att_src,
                           const float* __restrict__ att_dst) {
    int tid = threadIdx.x;   // 256
    if (tid == 0) { atomicAdd(&g_epoch, 1u); g_bigcnt = 0; }

    __shared__ float sv[LL][D];
    __shared__ float sgt[NV][D];
    int l = tid >> 6, j = tid & 63;
    float v = 0.f;
    #pragma unroll
    for (int k = 0; k < D; k++)
        v += att_edge[l * D + k] * W_edges[l * D * D + k * D + j];
    sv[l][j] = v;
    int vg = tid >> 6;
    for (int vv = vg; vv < NV; vv += 4) {
        float acc = 0.f;
        #pragma unroll
        for (int k = 0; k < D; k++)
            acc = fmaf(node_emb[vv * D + k], Ws[j * D + k], acc);
        sgt[vv][j] = acc;
        g_gt16[vv * D + j] = __float2half_rn(acc);
    }
    __syncthreads();
    if (tid < 16) {
        int ll = tid >> 2, a = tid & 3;
        float s = 0.f;
        for (int jj = 0; jj < D; jj++)
            s += edge_embs[ll * 4 * D + a * D + jj] * sv[ll][jj];
        g_ewalpha[ll * 4 + a] = s;
    }
    if (tid < NV) {
        float s = 0.f, dd = 0.f;
        #pragma unroll
        for (int jj = 0; jj < D; jj++) {
            s  += sgt[tid][jj] * att_src[jj];
            dd += sgt[tid][jj] * att_dst[jj];
        }
        g_ast[tid] = s;
        g_adt[tid] = dd;
    }
}

// ---------------- single-kernel scan (publish + spin) + layer-0 fill + big-list ----------------
__global__ void scanfill_kernel(const int* __restrict__ x) {
    __shared__ int wsum[8];
    __shared__ int soffset;
    __shared__ __align__(16) __half shalf[NV * D];
    int tid = threadIdx.x, lane = tid & 31, warp = tid >> 5;
    int b = blockIdx.x;
    unsigned epoch = g_epoch;

    int idx = b * 256 + tid;
    int v = (idx < NN) ? g_deg[idx] : 0;
    int xx = v;
    #pragma unroll
    for (int off = 1; off < 32; off <<= 1) {
        int t = __shfl_up_sync(0xFFFFFFFFu, xx, off);
        if (lane >= off) xx += t;
    }
    if (lane == 31) wsum[warp] = xx;
    __syncthreads();
    if (tid < 8) {
        int s = wsum[tid];
        #pragma unroll
        for (int off = 1; off < 8; off <<= 1) {
            int t = __shfl_up_sync(0xFFu, s, off);
            if (tid >= off) s += t;
        }
        wsum[tid] = s;
    }
    __syncthreads();
    int incl = xx + (warp ? wsum[warp - 1] : 0);

    if (tid == 255) {
        g_aggval[b] = incl;
        __threadfence();
        g_aggflag[b] = epoch;
    }
    if (warp == 0) {
        int sum = 0;
        for (int jj = lane; jj < b; jj += 32) {
            while (g_aggflag[jj] < epoch) { }
            sum += g_aggval[jj];
        }
        #pragma unroll
        for (int off = 16; off; off >>= 1)
            sum += __shfl_xor_sync(0xFFFFFFFFu, sum, off);
        if (lane == 0) soffset = sum;
    }
    __syncthreads();
    int r = incl + soffset;
    if (idx < NN) {
        g_rowptr[idx + 1] = r;
        if (v > 32) {
            int pos = atomicAdd(&g_bigcnt, 1);
            if (pos < MAXBIG) g_biglist[pos] = idx;
        }
    }
    if (b == 0 && tid == 0) g_rowptr[0] = 0;

    // ---- layer-0 fill: gbuf16/asrc/nodeinfo from tables ----
    for (int i = tid; i < (NV * D) / 8; i += 256)
        ((uint4*)shalf)[i] = ((const uint4*)g_gt16)[i];
    __syncthreads();
    if (idx < NN) {
        int xv = x[idx];
        g_asrc[idx] = g_ast[xv];
        int degc = (v < 255) ? v : 255;
        int packed = ((r - v) << 8) | degc;
        g_nodeinfo[idx] = make_float2(__int_as_float(packed), g_adt[xv]);
    }
    int nb = b * 256;
    for (int i = tid; i < 256 * 8; i += 256) {
        int nl = i >> 3, q = i & 7;
        int node = nb + nl;
        if (node < NN) {
            int xv = __ldg(&x[node]);
            ((uint4*)g_gbuf16)[node * 8 + q] = ((const uint4*)shalf)[xv * 8 + q];
        }
    }
}

// ---------------- scatter: atomic-free, pos = rowptr[dst] + erank (+ zero g_deg) ----------------
__global__ void scatter_kernel(const int* __restrict__ src,
                               const int* __restrict__ dst,
                               const int* __restrict__ attr) {
    int t = blockIdx.x * blockDim.x + threadIdx.x;
    int e = t * 4;
    if (e < NE) {
        int4 s = *(const int4*)(src + e);
        int4 d = *(const int4*)(dst + e);
        int4 a = *(const int4*)(attr + e);
        int4 r = *(const int4*)(g_erank + e);
        int p0 = __ldg(&g_rowptr[d.x]) + r.x;
        int p1 = __ldg(&g_rowptr[d.y]) + r.y;
        int p2 = __ldg(&g_rowptr[d.z]) + r.z;
        int p3 = __ldg(&g_rowptr[d.w]) + r.w;
        g_csr[p0] = (a.x << 24) | s.x;
        g_csr[p1] = (a.y << 24) | s.y;
        g_csr[p2] = (a.z << 24) | s.z;
        g_csr[p3] = (a.w << 24) | s.w;
    }
    if (t < NN) g_deg[t] = 0;
}

// ---------------- per-layer node GEMM (layers 1..3): 8x4 register-tiled ----------------
__global__ void __launch_bounds__(256) gemm_kernel(
        int layer,
        const float* __restrict__ Ws,
        const float* __restrict__ att_src,
        const float* __restrict__ att_dst,
        const float* __restrict__ biases) {
    __shared__ __align__(16) float shT[64][132];   // k-major, 128 nodes + pad
    __shared__ __align__(16) float sWT[64][68];    // sWT[k][j] = W[j][k]
    __shared__ float sred[2][16][128];

    const float* W = Ws + layer * D * D;
    const __half* in_h = (((layer - 1) & 1) == 0) ? g_h16A : g_h16B;
    const float* bias = biases + (layer - 1) * D;
    const float* a_s = att_src + layer * D;
    const float* a_d = att_dst + layer * D;

    int tid = threadIdx.x;
    int nb = blockIdx.x * 128;

    for (int idx = tid; idx < D * D; idx += 256) {
        sWT[idx & 63][idx >> 6] = W[idx];
    }
    // stage h (fp16 -> fp32 with bias+relu), half2 per thread-step
    for (int idx = tid; idx < 128 * 32; idx += 256) {
        int nl = idx >> 5, k2 = (idx & 31) * 2;
        int node = nb + nl;
        float h0 = 0.f, h1 = 0.f;
        if (node < NN) {
            __half2 hh = *(const __half2*)&in_h[node * D + k2];
            float2 f = __half22float2(hh);
            h0 = fmaxf(f.x + bias[k2], 0.f);
            h1 = fmaxf(f.y + bias[k2 + 1], 0.f);
        }
        shT[k2][nl]     = h0;
        shT[k2 + 1][nl] = h1;
    }
    __syncthreads();

    int tx = tid & 15;
    int ty = tid >> 4;
    int n0 = tx * 8;
    int j0 = ty * 4;

    float acc[8][4] = {};
    #pragma unroll 4
    for (int k = 0; k < 64; k++) {
        float4 ha = *(const float4*)&shT[k][n0];
        float4 hb = *(const float4*)&shT[k][n0 + 4];
        float4 wv = *(const float4*)&sWT[k][j0];
        #pragma unroll
        for (int i = 0; i < 4; i++) {
            float h = (i == 0) ? ha.x : (i == 1) ? ha.y : (i == 2) ? ha.z : ha.w;
            acc[i][0] = fmaf(h, wv.x, acc[i][0]);
            acc[i][1] = fmaf(h, wv.y, acc[i][1]);
            acc[i][2] = fmaf(h, wv.z, acc[i][2]);
            acc[i][3] = fmaf(h, wv.w, acc[i][3]);
        }
        #pragma unroll
        for (int i = 0; i < 4; i++) {
            float h = (i == 0) ? hb.x : (i == 1) ? hb.y : (i == 2) ? hb.z : hb.w;
            acc[4 + i][0] = fmaf(h, wv.x, acc[4 + i][0]);
            acc[4 + i][1] = fmaf(h, wv.y, acc[4 + i][1]);
            acc[4 + i][2] = fmaf(h, wv.z, acc[4 + i][2]);
            acc[4 + i][3] = fmaf(h, wv.w, acc[4 + i][3]);
        }
    }

    float as0 = a_s[j0], as1 = a_s[j0 + 1], as2 = a_s[j0 + 2], as3 = a_s[j0 + 3];
    float ad0 = a_d[j0], ad1 = a_d[j0 + 1], ad2 = a_d[j0 + 2], ad3 = a_d[j0 + 3];
    #pragma unroll
    for (int i = 0; i < 8; i++) {
        float sa = acc[i][0] * as0 + acc[i][1] * as1 + acc[i][2] * as2 + acc[i][3] * as3;
        float sd = acc[i][0] * ad0 + acc[i][1] * ad1 + acc[i][2] * ad2 + acc[i][3] * ad3;
        sred[0][ty][n0 + i] = sa;
        sred[1][ty][n0 + i] = sd;
        int node = nb + n0 + i;
        if (node < NN) {
            __half2 h01 = __floats2half2_rn(acc[i][0], acc[i][1]);
            __half2 h23 = __floats2half2_rn(acc[i][2], acc[i][3]);
            uint2 u;
            u.x = *(unsigned*)&h01;
            u.y = *(unsigned*)&h23;
            *(uint2*)&g_gbuf16[node * D + j0] = u;
        }
    }
    __syncthreads();
    if (tid < 128) {
        float s = 0.f, dsum = 0.f;
        #pragma unroll
        for (int t = 0; t < 16; t++) {
            s    += sred[0][t][tid];
            dsum += sred[1][t][tid];
        }
        int node = nb + tid;
        if (node < NN) {
            g_asrc[node] = s;
            ((float*)g_nodeinfo)[2 * node + 1] = dsum;   // .y only; .x stays
        }
    }
}

// ---------------- aggregation ----------------
// blocks [0, NORMB): warp per node, deg<=32 hot path only.
// blocks [NORMB, NORMB+BIGB): drain g_biglist (deg>32) via 3-pass fallback.
__global__ void __launch_bounds__(128) agg_kernel(int layer) {
    const unsigned F = 0xFFFFFFFFu;
    int lane = threadIdx.x & 31;
    const float* ewa = g_ewalpha + layer * 4;
    __half* out_h = ((layer & 1) == 0) ? g_h16A : g_h16B;
    int half  = lane >> 4;
    int qlane = lane & 15;
    const char* gb16 = (const char*)g_gbuf16 + (qlane << 3);
    float4 acc4 = make_float4(0.f, 0.f, 0.f, 0.f);

    if (blockIdx.x >= NORMB) {
        // -------- big-node path --------
        int gw = (blockIdx.x - NORMB) * 4 + (threadIdx.x >> 5);
        int cnt = g_bigcnt;
        if (cnt > MAXBIG) cnt = MAXBIG;
        for (int i = gw; i < cnt; i += BIGB * 4) {
            int n = g_biglist[i];
            int start = g_rowptr[n];
            int end   = g_rowptr[n + 1];
            float adst_n = g_nodeinfo[n].y;
            float m = -1e30f;
            for (int e = start + lane; e < end; e += 32) {
                int p = g_csr[e];
                float a = g_asrc[p & 0x00FFFFFF] + adst_n + ewa[p >> 24];
                a = (a > 0.f) ? a : NEG_SLOPE * a;
                g_alpha[e] = a;
                m = fmaxf(m, a);
            }
            #pragma unroll
            for (int off = 16; off; off >>= 1)
                m = fmaxf(m, __shfl_xor_sync(F, m, off));
            float s = 0.f;
            for (int e = start + lane; e < end; e += 32) {
                float ex = __expf(g_alpha[e] - m);
                g_alpha[e] = ex;
                s += ex;
            }
            #pragma unroll
            for (int off = 16; off; off >>= 1)
                s += __shfl_xor_sync(F, s, off);
            float inv = 1.f / (s + EPSV);

            float4 acc = make_float4(0.f, 0.f, 0.f, 0.f);
            for (int base = start; base < end; base += 32) {
                int c = min(32, end - base);
                float w = 0.f; int boff = 0;
                if (lane < c) {
                    int p = g_csr[base + lane];
                    boff = (p & 0x00FFFFFF) << 7;
                    w = g_alpha[base + lane] * inv;
                }
                for (int t = 0; t < c; t += 2) {
                    int e0 = (t + half) & 31;
                    float w0 = __shfl_sync(F, w, e0);
                    int   b0 = __shfl_sync(F, boff, e0);
                    uint2 u = *(const uint2*)(gb16 + b0);
                    float2 f0 = __half22float2(*(__half2*)&u.x);
                    float2 f1 = __half22float2(*(__half2*)&u.y);
                    acc.x = fmaf(w0, f0.x, acc.x);
                    acc.y = fmaf(w0, f0.y, acc.y);
                    acc.z = fmaf(w0, f1.x, acc.z);
                    acc.w = fmaf(w0, f1.y, acc.w);
                }
            }
            acc.x += __shfl_xor_sync(F, acc.x, 16);
            acc.y += __shfl_xor_sync(F, acc.y, 16);
            acc.z += __shfl_xor_sync(F, acc.z, 16);
            acc.w += __shfl_xor_sync(F, acc.w, 16);
            if (half == 0) {
                __half2 h01 = __floats2half2_rn(acc.x, acc.y);
                __half2 h23 = __floats2half2_rn(acc.z, acc.w);
                uint2 u;
                u.x = *(unsigned*)&h01;
                u.y = *(unsigned*)&h23;
                *(uint2*)&out_h[n * D + (qlane << 2)] = u;
            }
        }
        return;
    }

    // -------- hot path: warp per node, deg <= 32 --------
    int n = blockIdx.x * 4 + (threadIdx.x >> 5);
    if (n >= NN) return;
    float2 ni = g_nodeinfo[n];                  // one LDG.64: start/deg + adst
    int pk    = __float_as_int(ni.x);
    int start = pk >> 8;
    int deg   = pk & 255;
    if (deg > 32) return;                       // handled by big path (incl. saturated 255)
    if (deg == 0) {
        if (half == 0) {
            uint2 z = make_uint2(0u, 0u);
            *(uint2*)&out_h[n * D + (qlane << 2)] = z;
        }
        return;
    }

    float adst_n = ni.y;
    int p = 0;
    float a = -1e30f;
    if (lane < deg) {
        p = __ldg(&g_csr[start + lane]);
        a = g_asrc[p & 0x00FFFFFF] + adst_n + ewa[p >> 24];
        a = (a > 0.f) ? a : NEG_SLOPE * a;
    }
    float m = a;
    #pragma unroll
    for (int off = 16; off; off >>= 1)
        m = fmaxf(m, __shfl_xor_sync(F, m, off));
    float ex = __expf(a - m);                   // invalid lanes -> 0
    float s = ex;
    #pragma unroll
    for (int off = 16; off; off >>= 1)
        s += __shfl_xor_sync(F, s, off);
    float w = ex * (1.f / (s + EPSV));          // invalid lanes: 0
    int boff = (p & 0x00FFFFFF) << 7;           // byte offset of fp16 row

    // straight-line 8-edge blocks; padded lanes carry w=0 (harmless FMA).
#define EDGE8(T) { \
        int e0 = ((T)     + half) & 31; \
        int e1 = ((T) + 2 + half) & 31; \
        int e2 = ((T) + 4 + half) & 31; \
        int e3 = ((T) + 6 + half) & 31; \
        float w0 = __shfl_sync(F, w, e0);  int b0 = __shfl_sync(F, boff, e0); \
        float w1 = __shfl_sync(F, w, e1);  int b1 = __shfl_sync(F, boff, e1); \
        float w2 = __shfl_sync(F, w, e2);  int b2 = __shfl_sync(F, boff, e2); \
        float w3 = __shfl_sync(F, w, e3);  int b3 = __shfl_sync(F, boff, e3); \
        uint2 u0 = *(const uint2*)(gb16 + b0); \
        uint2 u1 = *(const uint2*)(gb16 + b1); \
        uint2 u2 = *(const uint2*)(gb16 + b2); \
        uint2 u3 = *(const uint2*)(gb16 + b3); \
        float2 f0a = __half22float2(*(__half2*)&u0.x); \
        float2 f0b = __half22float2(*(__half2*)&u0.y); \
        float2 f1a = __half22float2(*(__half2*)&u1.x); \
        float2 f1b = __half22float2(*(__half2*)&u1.y); \
        float2 f2a = __half22float2(*(__half2*)&u2.x); \
        float2 f2b = __half22float2(*(__half2*)&u2.y); \
        float2 f3a = __half22float2(*(__half2*)&u3.x); \
        float2 f3b = __half22float2(*(__half2*)&u3.y); \
        acc4.x = fmaf(w0, f0a.x, acc4.x); acc4.y = fmaf(w0, f0a.y, acc4.y); \
        acc4.z = fmaf(w0, f0b.x, acc4.z); acc4.w = fmaf(w0, f0b.y, acc4.w); \
        acc4.x = fmaf(w1, f1a.x, acc4.x); acc4.y = fmaf(w1, f1a.y, acc4.y); \
        acc4.z = fmaf(w1, f1b.x, acc4.z); acc4.w = fmaf(w1, f1b.y, acc4.w); \
        acc4.x = fmaf(w2, f2a.x, acc4.x); acc4.y = fmaf(w2, f2a.y, acc4.y); \
        acc4.z = fmaf(w2, f2b.x, acc4.z); acc4.w = fmaf(w2, f2b.y, acc4.w); \
        acc4.x = fmaf(w3, f3a.x, acc4.x); acc4.y = fmaf(w3, f3a.y, acc4.y); \
        acc4.z = fmaf(w3, f3b.x, acc4.z); acc4.w = fmaf(w3, f3b.y, acc4.w); \
    }

    if (deg <= 16) {
        EDGE8(0) EDGE8(8)
    } else if (deg <= 24) {
        EDGE8(0) EDGE8(8) EDGE8(16)
    } else {
        EDGE8(0) EDGE8(8) EDGE8(16) EDGE8(24)
    }
#undef EDGE8

    acc4.x += __shfl_xor_sync(F, acc4.x, 16);
    acc4.y += __shfl_xor_sync(F, acc4.y, 16);
    acc4.z += __shfl_xor_sync(F, acc4.z, 16);
    acc4.w += __shfl_xor_sync(F, acc4.w, 16);
    if (half == 0) {
        __half2 h01 = __floats2half2_rn(acc4.x, acc4.y);
        __half2 h23 = __floats2half2_rn(acc4.z, acc4.w);
        uint2 u;
        u.x = *(unsigned*)&h01;
        u.y = *(unsigned*)&h23;
        *(uint2*)&out_h[n * D + (qlane << 2)] = u;
    }
}

// ---------------- fused pooling + MLP: one block per graph ----------------
__global__ void __launch_bounds__(256) poolmlp_kernel(
        const int* __restrict__ batch,
        const float* __restrict__ biases,
        const float* __restrict__ W1, const float* __restrict__ b1,
        const float* __restrict__ W2, const float* __restrict__ b2,
        float* __restrict__ out) {
    __shared__ float sacc[4][D];
    __shared__ float sp[D];
    __shared__ float shid[2 * D];
    int g = blockIdx.x;
    int tid = threadIdx.x;   // 256

    int lo = 0, hi = NN;
    while (lo < hi) { int mid = (lo + hi) >> 1; if (batch[mid] < g) lo = mid + 1; else hi = mid; }
    int startn = lo;
    hi = NN;
    while (lo < hi) { int mid = (lo + hi) >> 1; if (batch[mid] <= g) lo = mid + 1; else hi = mid; }
    int endn = lo;

    int j = tid & 63, rg = tid >> 6;
    float bj = biases[3 * D + j];
    float acc = 0.f;
    for (int nn = startn + rg; nn < endn; nn += 4)
        acc += fmaxf(__half2float(g_h16B[nn * D + j]) + bj, 0.f);
    sacc[rg][j] = acc;
    __syncthreads();
    if (tid < D)
        sp[tid] = sacc[0][tid] + sacc[1][tid] + sacc[2][tid] + sacc[3][tid];
    __syncthreads();
    if (tid < 2 * D) {
        float hsum = b1[tid];
        #pragma unroll
        for (int k = 0; k < D; k++)
            hsum = fmaf(sp[k], W1[tid * D + k], hsum);
        shid[tid] = fmaxf(hsum, 0.f);
    }
    __syncthreads();
    if (tid < TT) {
        float o = b2[tid];
        #pragma unroll
        for (int k = 0; k < 2 * D; k++)
            o = fmaf(shid[k], W2[tid * 2 * D + k], o);
        out[g * TT + tid] = o;
    }
}

// ---------------- launch ----------------
extern "C" void kernel_launch(void* const* d_in, const int* in_sizes, int n_in,
                              void* d_out, int out_size) {
    const int*   x         = (const int*)  d_in[0];
    const int*   edge_idx  = (const int*)  d_in[1];
    const int*   edge_attr = (const int*)  d_in[2];
    const int*   batch     = (const int*)  d_in[3];
    const float* node_emb  = (const float*)d_in[4];
    const float* edge_embs = (const float*)d_in[5];
    const float* Ws        = (const float*)d_in[6];
    const float* W_edges   = (const float*)d_in[7];
    const float* att_src   = (const float*)d_in[8];
    const float* att_dst   = (const float*)d_in[9];
    const float* att_edge  = (const float*)d_in[10];
    const float* biases    = (const float*)d_in[11];
    const float* W1        = (const float*)d_in[12];
    const float* b1        = (const float*)d_in[13];
    const float* W2        = (const float*)d_in[14];
    const float* b2        = (const float*)d_in[15];
    float* out = (float*)d_out;

    const int* src = edge_idx;
    const int* dst = edge_idx + NE;

    int ethreads = NE / 4;                       // 200000
    int eblocks  = (ethreads + 255) / 256;       // 782

    hist_kernel<<<eblocks, 256>>>(dst);                                  // #1
    pre_kernel<<<1, 256>>>(edge_embs, W_edges, att_edge,
                           node_emb, Ws, att_src, att_dst);              // #2
    scanfill_kernel<<<NBLK, 256>>>(x);                                   // #3
    scatter_kernel<<<eblocks, 256>>>(src, dst, edge_attr);               // #4 -> profiled

    agg_kernel<<<NORMB + BIGB, 128>>>(0);
    for (int l = 1; l < LL; l++) {
        gemm_kernel<<<(NN + 127) / 128, 256>>>(l, Ws, att_src, att_dst, biases);
        agg_kernel<<<NORMB + BIGB, 128>>>(l);
    }

    poolmlp_kernel<<<GG, 256>>>(batch, biases, W1, b1, W2, b2, out);
}

// round 17
// speedup vs baseline: 1.0358x; 1.0358x over previous
#include <cuda_runtime.h>
#include <cuda_fp16.h>

#define NN 50000
#define NE 800000
#define D 64
#define LL 4
#define GG 128
#define TT 10
#define NEG_SLOPE 0.2f
#define EPSV 1e-16f
#define NBLK ((NN + 255) / 256)   // 196
#define NV 21                     // node vocab size
#define NORMB 12500               // agg blocks: warp per node, 4/block
#define BIGB 8                    // trailing agg blocks for deg>32 nodes
#define MAXBIG 8192

// ---------------- scratch (static __device__, zero-init at load) ----------------
__device__ int   g_deg[NN];        // zeroed by scatter_kernel at end of each run
__device__ int   g_rowptr[NN + 1];
__device__ int   g_erank[NE];      // per-edge rank within dst node (from hist)
__device__ unsigned g_epoch;                    // monotonic run counter
__device__ volatile unsigned g_aggflag[NBLK];   // epoch-tagged publish flags
__device__ volatile int      g_aggval[NBLK];
__device__ int   g_bigcnt;
__device__ int   g_biglist[MAXBIG];
__device__ int   g_csr[NE];        // packed (attr<<24) | src
__device__ float g_alpha[NE];      // big-node fallback scratch
__device__ float g_hA[NN * D];
__device__ float g_hB[NN * D];
__device__ __align__(16) __half g_gbuf16[NN * D];   // g in fp16 (1 line / row)
__device__ float g_asrc[NN];
__device__ float2 g_nodeinfo[NN];  // .x = int bits: (start<<8)|min(deg,255); .y = adst
__device__ float g_ewalpha[LL * 4];
__device__ __align__(16) __half g_gt16[NV * D];     // layer-0 g table (fp16)
__device__ float g_ast[NV];        // layer-0 asrc table
__device__ float g_adt[NV];        // layer-0 adst table

// ---------------- hist (4 edges/thread, capture rank) + epoch + ewalpha + layer-0 table ----------------
__global__ void hist_pre_kernel(const int* __restrict__ dst,
                                const float* __restrict__ edge_embs,
                                const float* __restrict__ W_edges,
                                const float* __restrict__ att_edge,
                                const float* __restrict__ node_emb,
                                const float* __restrict__ Ws,
                                const float* __restrict__ att_src,
                                const float* __restrict__ att_dst) {
    int tid = threadIdx.x;
    int t = blockIdx.x * 256 + tid;
    int e = t * 4;
    if (e < NE) {   // NE % 4 == 0
        int4 d = *(const int4*)(dst + e);
        int4 r;
        r.x = atomicAdd(&g_deg[d.x], 1);
        r.y = atomicAdd(&g_deg[d.y], 1);
        r.z = atomicAdd(&g_deg[d.z], 1);
        r.w = atomicAdd(&g_deg[d.w], 1);
        *(int4*)(g_erank + e) = r;
    }
    if (blockIdx.x == 0 && tid == 0) atomicAdd(&g_epoch, 1u);

    if (blockIdx.x == gridDim.x - 1) {
        if (tid == 0) g_bigcnt = 0;
        __shared__ float sv[LL][D];
        __shared__ float sgt[NV][D];
        int l = tid >> 6, j = tid & 63;
        float v = 0.f;
        #pragma unroll
        for (int k = 0; k < D; k++)
            v += att_edge[l * D + k] * W_edges[l * D * D + k * D + j];
        sv[l][j] = v;
        int vg = tid >> 6;
        for (int vv = vg; vv < NV; vv += 4) {
            float acc = 0.f;
            #pragma unroll
            for (int k = 0; k < D; k++)
                acc = fmaf(node_emb[vv * D + k], Ws[j * D + k], acc);
            sgt[vv][j] = acc;
            g_gt16[vv * D + j] = __float2half_rn(acc);
        }
        __syncthreads();
        if (tid < 16) {
            int ll = tid >> 2, a = tid & 3;
            float s = 0.f;
            for (int jj = 0; jj < D; jj++)
                s += edge_embs[ll * 4 * D + a * D + jj] * sv[ll][jj];
            g_ewalpha[ll * 4 + a] = s;
        }
        if (tid < NV) {
            float s = 0.f, dd = 0.f;
            #pragma unroll
            for (int jj = 0; jj < D; jj++) {
                s  += sgt[tid][jj] * att_src[jj];
                dd += sgt[tid][jj] * att_dst[jj];
            }
            g_ast[tid] = s;
            g_adt[tid] = dd;
        }
    }
}

// ---------------- single-kernel scan (publish + spin) + layer-0 fill + big-list ----------------
__global__ void scanfill_kernel(const int* __restrict__ x) {
    __shared__ int wsum[8];
    __shared__ int soffset;
    __shared__ __align__(16) __half shalf[NV * D];
    int tid = threadIdx.x, lane = tid & 31, warp = tid >> 5;
    int b = blockIdx.x;
    unsigned epoch = g_epoch;

    int idx = b * 256 + tid;
    int v = (idx < NN) ? g_deg[idx] : 0;
    int xx = v;
    #pragma unroll
    for (int off = 1; off < 32; off <<= 1) {
        int t = __shfl_up_sync(0xFFFFFFFFu, xx, off);
        if (lane >= off) xx += t;
    }
    if (lane == 31) wsum[warp] = xx;
    __syncthreads();
    if (tid < 8) {
        int s = wsum[tid];
        #pragma unroll
        for (int off = 1; off < 8; off <<= 1) {
            int t = __shfl_up_sync(0xFFu, s, off);
            if (tid >= off) s += t;
        }
        wsum[tid] = s;
    }
    __syncthreads();
    int incl = xx + (warp ? wsum[warp - 1] : 0);

    if (tid == 255) {
        g_aggval[b] = incl;
        __threadfence();
        g_aggflag[b] = epoch;
    }
    if (warp == 0) {
        int sum = 0;
        for (int jj = lane; jj < b; jj += 32) {
            while (g_aggflag[jj] < epoch) { }
            sum += g_aggval[jj];
        }
        #pragma unroll
        for (int off = 16; off; off >>= 1)
            sum += __shfl_xor_sync(0xFFFFFFFFu, sum, off);
        if (lane == 0) soffset = sum;
    }
    __syncthreads();
    int r = incl + soffset;
    if (idx < NN) {
        g_rowptr[idx + 1] = r;
        if (v > 32) {
            int pos = atomicAdd(&g_bigcnt, 1);
            if (pos < MAXBIG) g_biglist[pos] = idx;
        }
    }
    if (b == 0 && tid == 0) g_rowptr[0] = 0;

    // ---- layer-0 fill: gbuf16/asrc/nodeinfo from tables ----
    for (int i = tid; i < (NV * D) / 8; i += 256)
        ((uint4*)shalf)[i] = ((const uint4*)g_gt16)[i];
    __syncthreads();
    if (idx < NN) {
        int xv = x[idx];
        g_asrc[idx] = g_ast[xv];
        int degc = (v < 255) ? v : 255;
        int packed = ((r - v) << 8) | degc;
        g_nodeinfo[idx] = make_float2(__int_as_float(packed), g_adt[xv]);
    }
    int nb = b * 256;
    for (int i = tid; i < 256 * 8; i += 256) {
        int nl = i >> 3, q = i & 7;
        int node = nb + nl;
        if (node < NN) {
            int xv = __ldg(&x[node]);
            ((uint4*)g_gbuf16)[node * 8 + q] = ((const uint4*)shalf)[xv * 8 + q];
        }
    }
}

// ---------------- scatter: atomic-free, pos = rowptr[dst] + erank (+ zero g_deg) ----------------
__global__ void scatter_kernel(const int* __restrict__ src,
                               const int* __restrict__ dst,
                               const int* __restrict__ attr) {
    int t = blockIdx.x * blockDim.x + threadIdx.x;
    int e = t * 4;
    if (e < NE) {
        int4 s = *(const int4*)(src + e);
        int4 d = *(const int4*)(dst + e);
        int4 a = *(const int4*)(attr + e);
        int4 r = *(const int4*)(g_erank + e);
        int p0 = __ldg(&g_rowptr[d.x]) + r.x;
        int p1 = __ldg(&g_rowptr[d.y]) + r.y;
        int p2 = __ldg(&g_rowptr[d.z]) + r.z;
        int p3 = __ldg(&g_rowptr[d.w]) + r.w;
        g_csr[p0] = (a.x << 24) | s.x;
        g_csr[p1] = (a.y << 24) | s.y;
        g_csr[p2] = (a.z << 24) | s.z;
        g_csr[p3] = (a.w << 24) | s.w;
    }
    if (t < NN) g_deg[t] = 0;
}

// ---------------- per-layer node GEMM (layers 1..3): 8x4 register-tiled ----------------
__global__ void __launch_bounds__(256) gemm_kernel(
        int layer,
        const float* __restrict__ Ws,
        const float* __restrict__ att_src,
        const float* __restrict__ att_dst,
        const float* __restrict__ biases) {
    __shared__ __align__(16) float shT[64][132];   // k-major, 128 nodes + pad
    __shared__ __align__(16) float sWT[64][68];    // sWT[k][j] = W[j][k]
    __shared__ float sred[2][16][128];

    const float* W = Ws + layer * D * D;
    const float* in_h = (((layer - 1) & 1) == 0) ? g_hA : g_hB;
    const float* bias = biases + (layer - 1) * D;
    const float* a_s = att_src + layer * D;
    const float* a_d = att_dst + layer * D;

    int tid = threadIdx.x;
    int nb = blockIdx.x * 128;

    for (int idx = tid; idx < D * D; idx += 256) {
        sWT[idx & 63][idx >> 6] = W[idx];
    }
    for (int idx = tid; idx < 128 * D; idx += 256) {
        int nl = idx >> 6, k = idx & 63;
        int node = nb + nl;
        float hv = 0.f;
        if (node < NN)
            hv = fmaxf(in_h[node * D + k] + bias[k], 0.f);
        shT[k][nl] = hv;
    }
    __syncthreads();

    int tx = tid & 15;
    int ty = tid >> 4;
    int n0 = tx * 8;
    int j0 = ty * 4;

    float acc[8][4] = {};
    #pragma unroll 4
    for (int k = 0; k < 64; k++) {
        float4 ha = *(const float4*)&shT[k][n0];
        float4 hb = *(const float4*)&shT[k][n0 + 4];
        float4 wv = *(const float4*)&sWT[k][j0];
        #pragma unroll
        for (int i = 0; i < 4; i++) {
            float h = (i == 0) ? ha.x : (i == 1) ? ha.y : (i == 2) ? ha.z : ha.w;
            acc[i][0] = fmaf(h, wv.x, acc[i][0]);
            acc[i][1] = fmaf(h, wv.y, acc[i][1]);
            acc[i][2] = fmaf(h, wv.z, acc[i][2]);
            acc[i][3] = fmaf(h, wv.w, acc[i][3]);
        }
        #pragma unroll
        for (int i = 0; i < 4; i++) {
            float h = (i == 0) ? hb.x : (i == 1) ? hb.y : (i == 2) ? hb.z : hb.w;
            acc[4 + i][0] = fmaf(h, wv.x, acc[4 + i][0]);
            acc[4 + i][1] = fmaf(h, wv.y, acc[4 + i][1]);
            acc[4 + i][2] = fmaf(h, wv.z, acc[4 + i][2]);
            acc[4 + i][3] = fmaf(h, wv.w, acc[4 + i][3]);
        }
    }

    float as0 = a_s[j0], as1 = a_s[j0 + 1], as2 = a_s[j0 + 2], as3 = a_s[j0 + 3];
    float ad0 = a_d[j0], ad1 = a_d[j0 + 1], ad2 = a_d[j0 + 2], ad3 = a_d[j0 + 3];
    #pragma unroll
    for (int i = 0; i < 8; i++) {
        float sa = acc[i][0] * as0 + acc[i][1] * as1 + acc[i][2] * as2 + acc[i][3] * as3;
        float sd = acc[i][0] * ad0 + acc[i][1] * ad1 + acc[i][2] * ad2 + acc[i][3] * ad3;
        sred[0][ty][n0 + i] = sa;
        sred[1][ty][n0 + i] = sd;
        int node = nb + n0 + i;
        if (node < NN) {
            __half2 h01 = __floats2half2_rn(acc[i][0], acc[i][1]);
            __half2 h23 = __floats2half2_rn(acc[i][2], acc[i][3]);
            uint2 u;
            u.x = *(unsigned*)&h01;
            u.y = *(unsigned*)&h23;
            *(uint2*)&g_gbuf16[node * D + j0] = u;
        }
    }
    __syncthreads();
    if (tid < 128) {
        float s = 0.f, dsum = 0.f;
        #pragma unroll
        for (int t = 0; t < 16; t++) {
            s    += sred[0][t][tid];
            dsum += sred[1][t][tid];
        }
        int node = nb + tid;
        if (node < NN) {
            g_asrc[node] = s;
            ((float*)g_nodeinfo)[2 * node + 1] = dsum;   // .y only; .x stays
        }
    }
}

// ---------------- aggregation ----------------
// blocks [0, NORMB): warp per node, deg<=32 hot path only.
// blocks [NORMB, NORMB+BIGB): drain g_biglist (deg>32) via 3-pass fallback.
__global__ void __launch_bounds__(128) agg_kernel(int layer) {
    const unsigned F = 0xFFFFFFFFu;
    int lane = threadIdx.x & 31;
    const float* ewa = g_ewalpha + layer * 4;
    float* out_h = ((layer & 1) == 0) ? g_hA : g_hB;
    int half  = lane >> 4;
    int qlane = lane & 15;
    const char* gb16 = (const char*)g_gbuf16 + (qlane << 3);
    float4 acc4 = make_float4(0.f, 0.f, 0.f, 0.f);

    if (blockIdx.x >= NORMB) {
        // -------- big-node path --------
        int gw = (blockIdx.x - NORMB) * 4 + (threadIdx.x >> 5);
        int cnt = g_bigcnt;
        if (cnt > MAXBIG) cnt = MAXBIG;
        for (int i = gw; i < cnt; i += BIGB * 4) {
            int n = g_biglist[i];
            int start = g_rowptr[n];
            int end   = g_rowptr[n + 1];
            float adst_n = g_nodeinfo[n].y;
            float m = -1e30f;
            for (int e = start + lane; e < end; e += 32) {
                int p = g_csr[e];
                float a = g_asrc[p & 0x00FFFFFF] + adst_n + ewa[p >> 24];
                a = (a > 0.f) ? a : NEG_SLOPE * a;
                g_alpha[e] = a;
                m = fmaxf(m, a);
            }
            #pragma unroll
            for (int off = 16; off; off >>= 1)
                m = fmaxf(m, __shfl_xor_sync(F, m, off));
            float s = 0.f;
            for (int e = start + lane; e < end; e += 32) {
                float ex = __expf(g_alpha[e] - m);
                g_alpha[e] = ex;
                s += ex;
            }
            #pragma unroll
            for (int off = 16; off; off >>= 1)
                s += __shfl_xor_sync(F, s, off);
            float inv = 1.f / (s + EPSV);

            float4 acc = make_float4(0.f, 0.f, 0.f, 0.f);
            for (int base = start; base < end; base += 32) {
                int c = min(32, end - base);
                float w = 0.f; int boff = 0;
                if (lane < c) {
                    int p = g_csr[base + lane];
                    boff = (p & 0x00FFFFFF) << 7;
                    w = g_alpha[base + lane] * inv;
                }
                for (int t = 0; t < c; t += 2) {
                    int e0 = (t + half) & 31;
                    float w0 = __shfl_sync(F, w, e0);
                    int   b0 = __shfl_sync(F, boff, e0);
                    uint2 u = *(const uint2*)(gb16 + b0);
                    float2 f0 = __half22float2(*(__half2*)&u.x);
                    float2 f1 = __half22float2(*(__half2*)&u.y);
                    acc.x = fmaf(w0, f0.x, acc.x);
                    acc.y = fmaf(w0, f0.y, acc.y);
                    acc.z = fmaf(w0, f1.x, acc.z);
                    acc.w = fmaf(w0, f1.y, acc.w);
                }
            }
            acc.x += __shfl_xor_sync(F, acc.x, 16);
            acc.y += __shfl_xor_sync(F, acc.y, 16);
            acc.z += __shfl_xor_sync(F, acc.z, 16);
            acc.w += __shfl_xor_sync(F, acc.w, 16);
            if (half == 0)
                *(float4*)(out_h + n * D + (qlane << 2)) = acc;
        }
        return;
    }

    // -------- hot path: warp per node, deg <= 32 --------
    int n = blockIdx.x * 4 + (threadIdx.x >> 5);
    if (n >= NN) return;
    float2 ni = g_nodeinfo[n];                  // one LDG.64: start/deg + adst
    int pk    = __float_as_int(ni.x);
    int start = pk >> 8;
    int deg   = pk & 255;
    if (deg > 32) return;                       // handled by big path (incl. saturated 255)
    if (deg == 0) {
        if (half == 0)
            *(float4*)(out_h + n * D + (qlane << 2)) = acc4;
        return;
    }

    float adst_n = ni.y;
    int p = 0;
    float a = -1e30f;
    if (lane < deg) {
        p = __ldg(&g_csr[start + lane]);
        a = g_asrc[p & 0x00FFFFFF] + adst_n + ewa[p >> 24];
        a = (a > 0.f) ? a : NEG_SLOPE * a;
    }
    float m = a;
    #pragma unroll
    for (int off = 16; off; off >>= 1)
        m = fmaxf(m, __shfl_xor_sync(F, m, off));
    float ex = __expf(a - m);                   // invalid lanes -> 0
    float s = ex;
    #pragma unroll
    for (int off = 16; off; off >>= 1)
        s += __shfl_xor_sync(F, s, off);
    float w = ex * (1.f / (s + EPSV));          // invalid lanes: 0
    int boff = (p & 0x00FFFFFF) << 7;           // byte offset of fp16 row

    // straight-line 8-edge blocks; padded lanes carry w=0 (harmless FMA).
#define EDGE8(T) { \
        int e0 = ((T)     + half) & 31; \
        int e1 = ((T) + 2 + half) & 31; \
        int e2 = ((T) + 4 + half) & 31; \
        int e3 = ((T) + 6 + half) & 31; \
        float w0 = __shfl_sync(F, w, e0);  int b0 = __shfl_sync(F, boff, e0); \
        float w1 = __shfl_sync(F, w, e1);  int b1 = __shfl_sync(F, boff, e1); \
        float w2 = __shfl_sync(F, w, e2);  int b2 = __shfl_sync(F, boff, e2); \
        float w3 = __shfl_sync(F, w, e3);  int b3 = __shfl_sync(F, boff, e3); \
        uint2 u0 = *(const uint2*)(gb16 + b0); \
        uint2 u1 = *(const uint2*)(gb16 + b1); \
        uint2 u2 = *(const uint2*)(gb16 + b2); \
        uint2 u3 = *(const uint2*)(gb16 + b3); \
        float2 f0a = __half22float2(*(__half2*)&u0.x); \
        float2 f0b = __half22float2(*(__half2*)&u0.y); \
        float2 f1a = __half22float2(*(__half2*)&u1.x); \
        float2 f1b = __half22float2(*(__half2*)&u1.y); \
        float2 f2a = __half22float2(*(__half2*)&u2.x); \
        float2 f2b = __half22float2(*(__half2*)&u2.y); \
        float2 f3a = __half22float2(*(__half2*)&u3.x); \
        float2 f3b = __half22float2(*(__half2*)&u3.y); \
        acc4.x = fmaf(w0, f0a.x, acc4.x); acc4.y = fmaf(w0, f0a.y, acc4.y); \
        acc4.z = fmaf(w0, f0b.x, acc4.z); acc4.w = fmaf(w0, f0b.y, acc4.w); \
        acc4.x = fmaf(w1, f1a.x, acc4.x); acc4.y = fmaf(w1, f1a.y, acc4.y); \
        acc4.z = fmaf(w1, f1b.x, acc4.z); acc4.w = fmaf(w1, f1b.y, acc4.w); \
        acc4.x = fmaf(w2, f2a.x, acc4.x); acc4.y = fmaf(w2, f2a.y, acc4.y); \
        acc4.z = fmaf(w2, f2b.x, acc4.z); acc4.w = fmaf(w2, f2b.y, acc4.w); \
        acc4.x = fmaf(w3, f3a.x, acc4.x); acc4.y = fmaf(w3, f3a.y, acc4.y); \
        acc4.z = fmaf(w3, f3b.x, acc4.z); acc4.w = fmaf(w3, f3b.y, acc4.w); \
    }

    if (deg <= 16) {
        EDGE8(0) EDGE8(8)
    } else if (deg <= 24) {
        EDGE8(0) EDGE8(8) EDGE8(16)
    } else {
        EDGE8(0) EDGE8(8) EDGE8(16) EDGE8(24)
    }
#undef EDGE8

    acc4.x += __shfl_xor_sync(F, acc4.x, 16);
    acc4.y += __shfl_xor_sync(F, acc4.y, 16);
    acc4.z += __shfl_xor_sync(F, acc4.z, 16);
    acc4.w += __shfl_xor_sync(F, acc4.w, 16);
    if (half == 0)
        *(float4*)(out_h + n * D + (qlane << 2)) = acc4;
}

// ---------------- fused pooling + MLP: one block per graph ----------------
__global__ void __launch_bounds__(256) poolmlp_kernel(
        const int* __restrict__ batch,
        const float* __restrict__ biases,
        const float* __restrict__ W1, const float* __restrict__ b1,
        const float* __restrict__ W2, const float* __restrict__ b2,
        float* __restrict__ out) {
    __shared__ float sacc[4][D];
    __shared__ float sp[D];
    __shared__ float shid[2 * D];
    int g = blockIdx.x;
    int tid = threadIdx.x;   // 256

    int lo = 0, hi = NN;
    while (lo < hi) { int mid = (lo + hi) >> 1; if (batch[mid] < g) lo = mid + 1; else hi = mid; }
    int startn = lo;
    hi = NN;
    while (lo < hi) { int mid = (lo + hi) >> 1; if (batch[mid] <= g) lo = mid + 1; else hi = mid; }
    int endn = lo;

    int j = tid & 63, rg = tid >> 6;
    float bj = biases[3 * D + j];
    float acc = 0.f;
    for (int nn = startn + rg; nn < endn; nn += 4)
        acc += fmaxf(g_hB[nn * D + j] + bj, 0.f);
    sacc[rg][j] = acc;
    __syncthreads();
    if (tid < D)
        sp[tid] = sacc[0][tid] + sacc[1][tid] + sacc[2][tid] + sacc[3][tid];
    __syncthreads();
    if (tid < 2 * D) {
        float hsum = b1[tid];
        #pragma unroll
        for (int k = 0; k < D; k++)
            hsum = fmaf(sp[k], W1[tid * D + k], hsum);
        shid[tid] = fmaxf(hsum, 0.f);
    }
    __syncthreads();
    if (tid < TT) {
        float o = b2[tid];
        #pragma unroll
        for (int k = 0; k < 2 * D; k++)
            o = fmaf(shid[k], W2[tid * 2 * D + k], o);
        out[g * TT + tid] = o;
    }
}

// ---------------- launch ----------------
extern "C" void kernel_launch(void* const* d_in, const int* in_sizes, int n_in,
                              void* d_out, int out_size) {
    const int*   x         = (const int*)  d_in[0];
    const int*   edge_idx  = (const int*)  d_in[1];
    const int*   edge_attr = (const int*)  d_in[2];
    const int*   batch     = (const int*)  d_in[3];
    const float* node_emb  = (const float*)d_in[4];
    const float* edge_embs = (const float*)d_in[5];
    const float* Ws        = (const float*)d_in[6];
    const float* W_edges   = (const float*)d_in[7];
    const float* att_src   = (const float*)d_in[8];
    const float* att_dst   = (const float*)d_in[9];
    const float* att_edge  = (const float*)d_in[10];
    const float* biases    = (const float*)d_in[11];
    const float* W1        = (const float*)d_in[12];
    const float* b1        = (const float*)d_in[13];
    const float* W2        = (const float*)d_in[14];
    const float* b2        = (const float*)d_in[15];
    float* out = (float*)d_out;

    const int* src = edge_idx;
    const int* dst = edge_idx + NE;

    int ethreads = NE / 4;                       // 200000
    int eblocks  = (ethreads + 255) / 256;       // 782

    hist_pre_kernel<<<eblocks + 1, 256>>>(dst, edge_embs, W_edges, att_edge,
                                          node_emb, Ws, att_src, att_dst);
    scanfill_kernel<<<NBLK, 256>>>(x);
    scatter_kernel<<<eblocks, 256>>>(src, dst, edge_attr);

    agg_kernel<<<NORMB + BIGB, 128>>>(0);   // launch #4 -> profiled
    for (int l = 1; l < LL; l++) {
        gemm_kernel<<<(NN + 127) / 128, 256>>>(l, Ws, att_src, att_dst, biases);
        agg_kernel<<<NORMB + BIGB, 128>>>(l);
    }

    poolmlp_kernel<<<GG, 256>>>(batch, biases, W1, b1, W2, b2, out);
}